// round 10
// baseline (speedup 1.0000x reference)
#include <cuda_runtime.h>
#include <math.h>
#include <stdint.h>

// Problem constants (B=8, T=2048, C=1024, H=16, d=64)
#define B_  8
#define T_  2048
#define C_  1024
#define H_  16
#define D_  64
#define M_TOT 16384
#define N_TOT 3072
#define K_TOT 1024

// q/k/v scratch in (B,H,T,d) layout, values pre-rounded to tf32 bit patterns.
__device__ float g_q[B_ * H_ * T_ * D_];
__device__ float g_k[B_ * H_ * T_ * D_];
__device__ float g_v[B_ * H_ * T_ * D_];
// tf32-pre-rounded copies of X and W (so the GEMM mainloop has zero cvts).
__device__ float g_xr[(size_t)M_TOT * K_TOT];
__device__ float g_wr[(size_t)K_TOT * N_TOT];

// ---------------------------------------------------------------------------
// Helpers
// ---------------------------------------------------------------------------
__device__ __forceinline__ uint32_t cvt_tf32(float x) {
    uint32_t r;
    asm("cvt.rna.tf32.f32 %0, %1;" : "=r"(r) : "f"(x));
    return r;
}

// D += A(16x8) * B(8x8), tf32 inputs, f32 accumulate.
__device__ __forceinline__ void mma_tf32(float* d, const uint32_t* a,
                                         uint32_t b0, uint32_t b1) {
    asm volatile(
        "mma.sync.aligned.m16n8k8.row.col.f32.tf32.tf32.f32 "
        "{%0,%1,%2,%3}, {%4,%5,%6,%7}, {%8,%9}, {%0,%1,%2,%3};"
        : "+f"(d[0]), "+f"(d[1]), "+f"(d[2]), "+f"(d[3])
        : "r"(a[0]), "r"(a[1]), "r"(a[2]), "r"(a[3]), "r"(b0), "r"(b1));
}

__device__ __forceinline__ uint32_t smem_u32(const void* p) {
    uint32_t a;
    asm("{ .reg .u64 t; cvta.to.shared.u64 t, %1; cvt.u32.u64 %0, t; }"
        : "=r"(a) : "l"(p));
    return a;
}
__device__ __forceinline__ void cp16(uint32_t s, const void* g) {
    asm volatile("cp.async.cg.shared.global [%0], [%1], 16;" :: "r"(s), "l"(g));
}
#define CP_COMMIT() asm volatile("cp.async.commit_group;" ::: "memory")
#define CP_WAIT0()  asm volatile("cp.async.wait_group 0;" ::: "memory")
#define CP_WAIT1()  asm volatile("cp.async.wait_group 1;" ::: "memory")

// Named barrier for a 128-thread warp group (ids 1 and 2).
__device__ __forceinline__ void bar_g(int id) {
    asm volatile("bar.sync %0, 128;" :: "r"(id) : "memory");
}

// ---------------------------------------------------------------------------
// Kernel 0: elementwise tf32 pre-round into device globals
// ---------------------------------------------------------------------------
__global__ __launch_bounds__(256)
void round_x_pass(const float4* __restrict__ in)
{
    float4* out = (float4*)g_xr;
    int n4 = (M_TOT * K_TOT) / 4;
    int i = blockIdx.x * blockDim.x + threadIdx.x;
    int stride = gridDim.x * blockDim.x;
    for (; i < n4; i += stride) {
        float4 v = in[i];
        v.x = __uint_as_float(cvt_tf32(v.x));
        v.y = __uint_as_float(cvt_tf32(v.y));
        v.z = __uint_as_float(cvt_tf32(v.z));
        v.w = __uint_as_float(cvt_tf32(v.w));
        out[i] = v;
    }
}

__global__ __launch_bounds__(256)
void round_w_pass(const float4* __restrict__ in)
{
    float4* out = (float4*)g_wr;
    int n4 = (K_TOT * N_TOT) / 4;
    int i = blockIdx.x * blockDim.x + threadIdx.x;
    int stride = gridDim.x * blockDim.x;
    for (; i < n4; i += stride) {
        float4 v = in[i];
        v.x = __uint_as_float(cvt_tf32(v.x));
        v.y = __uint_as_float(cvt_tf32(v.y));
        v.z = __uint_as_float(cvt_tf32(v.z));
        v.w = __uint_as_float(cvt_tf32(v.w));
        out[i] = v;
    }
}

// ---------------------------------------------------------------------------
// Kernel 1: QKV GEMM via mma.sync tf32 on pre-rounded inputs (unchanged).
// ---------------------------------------------------------------------------
#define APITCH 36
#define BPITCH 136
#define ASZ (128 * APITCH)
#define BSZ (32 * BPITCH)
#define GEMM_SMEM_BYTES ((2 * ASZ + 2 * BSZ) * 4)

__device__ __forceinline__ void gemm_stage(const float* __restrict__ X,
                                           const float* __restrict__ W,
                                           int m0, int n0, int k0, int tid,
                                           uint32_t sA, uint32_t sB)
{
#pragma unroll
    for (int it = 0; it < 4; ++it) {          // A: 128 rows x 32 floats
        int f   = it * 256 + tid;
        int row = f >> 3;
        int seg = f & 7;
        cp16(sA + (row * APITCH + seg * 4) * 4,
             X + (size_t)(m0 + row) * K_TOT + k0 + seg * 4);
    }
#pragma unroll
    for (int it = 0; it < 4; ++it) {          // B: 32 rows x 128 floats
        int f   = it * 256 + tid;
        int row = f >> 5;
        int seg = f & 31;
        cp16(sB + (row * BPITCH + seg * 4) * 4,
             W + (size_t)(k0 + row) * N_TOT + n0 + seg * 4);
    }
}

__global__ __launch_bounds__(256)
void qkv_gemm_mma(const float* __restrict__ bias)
{
    extern __shared__ float sm[];
    float* A0 = sm;
    float* A1 = sm + ASZ;
    float* B0 = sm + 2 * ASZ;
    float* B1 = B0 + BSZ;

    const int tid  = threadIdx.x;
    const int wid  = tid >> 5;
    const int lane = tid & 31;
    const int gid  = lane >> 2;
    const int tig  = lane & 3;
    const int n0   = blockIdx.x * 128;
    const int m0   = blockIdx.y * 128;
    const int warp_m = (wid >> 2) * 64;
    const int warp_n = (wid & 3) * 32;

    const uint32_t sA0 = smem_u32(A0), sA1 = smem_u32(A1);
    const uint32_t sB0 = smem_u32(B0), sB1 = smem_u32(B1);
    const float* X = g_xr;
    const float* W = g_wr;

    float acc[4][4][4];
#pragma unroll
    for (int mi = 0; mi < 4; ++mi)
#pragma unroll
        for (int ni = 0; ni < 4; ++ni)
#pragma unroll
            for (int r = 0; r < 4; ++r) acc[mi][ni][r] = 0.f;

    gemm_stage(X, W, m0, n0, 0, tid, sA0, sB0);
    CP_COMMIT();

    for (int it = 0; it < 32; ++it) {
        if (it < 31) {
            gemm_stage(X, W, m0, n0, (it + 1) * 32, tid,
                       (it & 1) ? sA0 : sA1, (it & 1) ? sB0 : sB1);
            CP_COMMIT();
            CP_WAIT1();
        } else {
            CP_WAIT0();
        }
        __syncthreads();

        const uint32_t* A = (const uint32_t*)((it & 1) ? A1 : A0);
        const uint32_t* B = (const uint32_t*)((it & 1) ? B1 : B0);

#pragma unroll
        for (int s = 0; s < 4; ++s) {         // 4 ksteps of k=8
            uint32_t af[4][4];
#pragma unroll
            for (int mi = 0; mi < 4; ++mi) {
                int r0 = warp_m + mi * 16 + gid;
                int kc = s * 8 + tig;
                af[mi][0] = A[r0 * APITCH + kc];
                af[mi][1] = A[(r0 + 8) * APITCH + kc];
                af[mi][2] = A[r0 * APITCH + kc + 4];
                af[mi][3] = A[(r0 + 8) * APITCH + kc + 4];
            }
            uint32_t bf[4][2];
#pragma unroll
            for (int ni = 0; ni < 4; ++ni) {
                int nc = warp_n + ni * 8 + gid;
                int kc = s * 8 + tig;
                bf[ni][0] = B[kc * BPITCH + nc];
                bf[ni][1] = B[(kc + 4) * BPITCH + nc];
            }
#pragma unroll
            for (int mi = 0; mi < 4; ++mi)
#pragma unroll
                for (int ni = 0; ni < 4; ++ni)
                    mma_tf32(acc[mi][ni], af[mi], bf[ni][0], bf[ni][1]);
        }
        __syncthreads();
    }

    // Epilogue: add bias (fp32), round to tf32 bits, scatter into q/k/v.
#pragma unroll
    for (int mi = 0; mi < 4; ++mi) {
        int m = m0 + warp_m + mi * 16 + gid;
        int b = m >> 11;
        int t = m & 2047;
#pragma unroll
        for (int ni = 0; ni < 4; ++ni) {
            int n = n0 + warp_n + ni * 8 + 2 * tig;
            float bi0 = __ldg(bias + n);
            float bi1 = __ldg(bias + n + 1);
            int which = n >> 10;
            int cidx  = n & 1023;
            int h     = cidx >> 6;
            int dd    = cidx & 63;
            float* dst = (which == 0) ? g_q : ((which == 1) ? g_k : g_v);
            dst += ((size_t)((b << 4) + h) * 2048) * 64;
            float2 v0 = make_float2(__uint_as_float(cvt_tf32(acc[mi][ni][0] + bi0)),
                                    __uint_as_float(cvt_tf32(acc[mi][ni][1] + bi1)));
            float2 v1 = make_float2(__uint_as_float(cvt_tf32(acc[mi][ni][2] + bi0)),
                                    __uint_as_float(cvt_tf32(acc[mi][ni][3] + bi1)));
            *(float2*)(dst + (size_t)t * 64 + dd)       = v0;
            *(float2*)(dst + (size_t)(t + 8) * 64 + dd) = v1;
        }
    }
}

// ---------------------------------------------------------------------------
// Kernel 2: flash attention, 2 m16-tiles per warp, TWO FREE-RUNNING WARP
// GROUPS of 4 warps each. Each group owns private double-buffered K/V tiles
// and a private mask slice, synchronized with named barriers only -> the
// groups drift out of phase so one group's softmax (MUFU/shuffle) overlaps
// the other group's MMAs on the same SMSPs (R9 showed tensor pinned at ~48%
// by barrier-enforced phase serialization).
// ---------------------------------------------------------------------------
#define QP 68
#define KP 68
#define VP 72
#define PSTG (256 * QP)
#define KSZ  (64 * KP)
#define VSZ  (64 * VP)
// layout: Pst | K[4] (g0s0,g0s1,g1s0,g1s1) | V[4] | Ms[2][64]
#define FLASH_SMEM_BYTES ((PSTG + 4 * KSZ + 4 * VSZ + 128) * 4)

// Stage one 64-key K and V tile with 128 threads (one group).
__device__ __forceinline__ void kv_stage_g(int base, int kb, int lt,
                                           uint32_t sK, uint32_t sV)
{
#pragma unroll
    for (int it = 0; it < 8; ++it) {
        int f   = it * 128 + lt;       // 0..1023 float4 ids
        int row = f >> 4;
        int seg = f & 15;
        cp16(sK + (row * KP + seg * 4) * 4, g_k + (size_t)base + (kb + row) * 64 + seg * 4);
        cp16(sV + (row * VP + seg * 4) * 4, g_v + (size_t)base + (kb + row) * 64 + seg * 4);
    }
}

__global__ __launch_bounds__(256, 1)
void flash_attn_mma(const int* __restrict__ mask, float* __restrict__ out)
{
    extern __shared__ float sm[];
    float* Pst = sm;                          // Q stage -> per-warp P (256 rows)
    float* Kb  = sm + PSTG;                   // 4 K tiles
    float* Vb  = Kb + 4 * KSZ;                // 4 V tiles
    int*   Msb = (int*)(Vb + 4 * VSZ);        // 2 x 64 mask ints

    const int tid  = threadIdx.x;
    const int wid  = tid >> 5;
    const int lane = tid & 31;
    const int gid  = lane >> 2;
    const int tig  = lane & 3;
    const int grp  = wid >> 2;                // warp group 0 or 1
    const int lt   = tid & 127;               // thread id within group
    const int bh   = blockIdx.y;
    const int b    = bh >> 4;
    const int h    = bh & 15;
    const int q0   = blockIdx.x * 256;
    const int base = bh * (T_ * D_);

    float* Kg0 = Kb + (grp * 2 + 0) * KSZ;
    float* Kg1 = Kb + (grp * 2 + 1) * KSZ;
    float* Vg0 = Vb + (grp * 2 + 0) * VSZ;
    float* Vg1 = Vb + (grp * 2 + 1) * VSZ;
    int*   Ms  = Msb + grp * 64;
    const uint32_t sK0 = smem_u32(Kg0), sK1 = smem_u32(Kg1);
    const uint32_t sV0 = smem_u32(Vg0), sV1 = smem_u32(Vg1);
    const int bid = 1 + grp;                  // named barrier id

    // Stage Q (x 0.125, exact on tf32 values): 256 rows x 64 cols, all threads.
#pragma unroll
    for (int it = 0; it < 16; ++it) {
        int f   = it * 256 + tid;
        int row = f >> 4;
        int seg = f & 15;
        float4 v = *(const float4*)(g_q + (size_t)base + (q0 + row) * 64 + seg * 4);
        v.x *= 0.125f; v.y *= 0.125f; v.z *= 0.125f; v.w *= 0.125f;
        *(float4*)&Pst[row * QP + seg * 4] = v;
    }
    __syncthreads();   // last CTA-wide barrier; groups free-run after this

    // Q fragments for BOTH m16 tiles of this warp (rows wid*32 + mt*16 + ...)
    uint32_t qa[2][8][4];
    {
        const uint32_t* Pu = (const uint32_t*)Pst;
#pragma unroll
        for (int mt = 0; mt < 2; ++mt) {
            int r0 = wid * 32 + mt * 16 + gid;
#pragma unroll
            for (int s = 0; s < 8; ++s) {
                int kc = s * 8 + tig;
                qa[mt][s][0] = Pu[r0 * QP + kc];
                qa[mt][s][1] = Pu[(r0 + 8) * QP + kc];
                qa[mt][s][2] = Pu[r0 * QP + kc + 4];
                qa[mt][s][3] = Pu[(r0 + 8) * QP + kc + 4];
            }
        }
    }
    float* Pw = Pst + wid * 32 * QP;       // this warp's 32 rows (just fragged)

    float o[2][8][4];
#pragma unroll
    for (int mt = 0; mt < 2; ++mt)
#pragma unroll
        for (int j = 0; j < 8; ++j)
#pragma unroll
            for (int r = 0; r < 4; ++r) o[mt][j][r] = 0.f;
    float mrow[2][2], lrow[2][2];
#pragma unroll
    for (int mt = 0; mt < 2; ++mt) {
        mrow[mt][0] = -1e30f; mrow[mt][1] = -1e30f;
        lrow[mt][0] = 0.f;    lrow[mt][1] = 0.f;
    }

    // Q-frag read from Pst complete within the group before Pw writes happen;
    // warps only write their own Pw region, and the first Pw write is after
    // this group's first named barrier anyway via the mainloop structure.
    kv_stage_g(base, 0, lt, sK0, sV0);
    CP_COMMIT();

    for (int it = 0; it < 32; ++it) {
        const int kb = it * 64;
        if (it < 31) {
            kv_stage_g(base, kb + 64, lt,
                       (it & 1) ? sK0 : sK1, (it & 1) ? sV0 : sV1);
            CP_COMMIT();
            CP_WAIT1();
        } else {
            CP_WAIT0();
        }
        if (lt < 64) Ms[lt] = mask[b * T_ + kb + lt];
        bar_g(bid);   // group-local: K/V tiles + mask visible

        const uint32_t* Ks = (const uint32_t*)((it & 1) ? Kg1 : Kg0);
        const uint32_t* Vs = (const uint32_t*)((it & 1) ? Vg1 : Vg0);

        // S = Q . K^T — each K fragment feeds both m-tiles
        float s[2][8][4];
#pragma unroll
        for (int mt = 0; mt < 2; ++mt)
#pragma unroll
            for (int j = 0; j < 8; ++j)
#pragma unroll
                for (int r = 0; r < 4; ++r) s[mt][j][r] = 0.f;
#pragma unroll
        for (int st = 0; st < 8; ++st) {
            int kc = st * 8 + tig;
#pragma unroll
            for (int j = 0; j < 8; ++j) {
                int key = j * 8 + gid;
                uint32_t b0 = Ks[key * KP + kc];
                uint32_t b1 = Ks[key * KP + kc + 4];
                mma_tf32(s[0][j], qa[0][st], b0, b1);
                mma_tf32(s[1][j], qa[1][st], b0, b1);
            }
        }

        // Mask (same key columns for both tiles)
#pragma unroll
        for (int j = 0; j < 8; ++j) {
            int ca = j * 8 + 2 * tig;
            if (Ms[ca] == 0) {
                s[0][j][0] = -INFINITY; s[0][j][2] = -INFINITY;
                s[1][j][0] = -INFINITY; s[1][j][2] = -INFINITY;
            }
            if (Ms[ca + 1] == 0) {
                s[0][j][1] = -INFINITY; s[0][j][3] = -INFINITY;
                s[1][j][1] = -INFINITY; s[1][j][3] = -INFINITY;
            }
        }

        // Online softmax per tile (rows gid, gid+8 within each tile)
#pragma unroll
        for (int mt = 0; mt < 2; ++mt) {
            float rm0 = -INFINITY, rm1 = -INFINITY;
#pragma unroll
            for (int j = 0; j < 8; ++j) {
                rm0 = fmaxf(rm0, fmaxf(s[mt][j][0], s[mt][j][1]));
                rm1 = fmaxf(rm1, fmaxf(s[mt][j][2], s[mt][j][3]));
            }
            rm0 = fmaxf(rm0, __shfl_xor_sync(0xffffffffu, rm0, 1));
            rm0 = fmaxf(rm0, __shfl_xor_sync(0xffffffffu, rm0, 2));
            rm1 = fmaxf(rm1, __shfl_xor_sync(0xffffffffu, rm1, 1));
            rm1 = fmaxf(rm1, __shfl_xor_sync(0xffffffffu, rm1, 2));

            float mn0 = fmaxf(mrow[mt][0], rm0), mn1 = fmaxf(mrow[mt][1], rm1);
            float sc0 = __expf(mrow[mt][0] - mn0), sc1 = __expf(mrow[mt][1] - mn1);
            mrow[mt][0] = mn0; mrow[mt][1] = mn1;

            float rs0 = 0.f, rs1 = 0.f;
#pragma unroll
            for (int j = 0; j < 8; ++j) {
                s[mt][j][0] = __expf(s[mt][j][0] - mn0); rs0 += s[mt][j][0];
                s[mt][j][1] = __expf(s[mt][j][1] - mn0); rs0 += s[mt][j][1];
                s[mt][j][2] = __expf(s[mt][j][2] - mn1); rs1 += s[mt][j][2];
                s[mt][j][3] = __expf(s[mt][j][3] - mn1); rs1 += s[mt][j][3];
            }
            rs0 += __shfl_xor_sync(0xffffffffu, rs0, 1);
            rs0 += __shfl_xor_sync(0xffffffffu, rs0, 2);
            rs1 += __shfl_xor_sync(0xffffffffu, rs1, 1);
            rs1 += __shfl_xor_sync(0xffffffffu, rs1, 2);
            lrow[mt][0] = lrow[mt][0] * sc0 + rs0;
            lrow[mt][1] = lrow[mt][1] * sc1 + rs1;

#pragma unroll
            for (int j = 0; j < 8; ++j) {
                o[mt][j][0] *= sc0; o[mt][j][1] *= sc0;
                o[mt][j][2] *= sc1; o[mt][j][3] *= sc1;
            }

            // P for this tile to warp-private smem (tf32-rounded)
#pragma unroll
            for (int j = 0; j < 8; ++j) {
                int col = j * 8 + 2 * tig;
                float2 p0 = make_float2(__uint_as_float(cvt_tf32(s[mt][j][0])),
                                        __uint_as_float(cvt_tf32(s[mt][j][1])));
                float2 p1 = make_float2(__uint_as_float(cvt_tf32(s[mt][j][2])),
                                        __uint_as_float(cvt_tf32(s[mt][j][3])));
                *(float2*)&Pw[(mt * 16 + gid) * QP + col]     = p0;
                *(float2*)&Pw[(mt * 16 + gid + 8) * QP + col] = p1;
            }
        }
        __syncwarp();

        // O += P . V — each V fragment feeds both m-tiles
        const uint32_t* Pwu = (const uint32_t*)Pw;
#pragma unroll
        for (int st = 0; st < 8; ++st) {
            int kc = st * 8 + tig;
            uint32_t pa[2][4];
#pragma unroll
            for (int mt = 0; mt < 2; ++mt) {
                pa[mt][0] = Pwu[(mt * 16 + gid) * QP + kc];
                pa[mt][1] = Pwu[(mt * 16 + gid + 8) * QP + kc];
                pa[mt][2] = Pwu[(mt * 16 + gid) * QP + kc + 4];
                pa[mt][3] = Pwu[(mt * 16 + gid + 8) * QP + kc + 4];
            }
#pragma unroll
            for (int j = 0; j < 8; ++j) {
                int dc = j * 8 + gid;
                uint32_t b0 = Vs[kc * VP + dc];
                uint32_t b1 = Vs[(kc + 4) * VP + dc];
                mma_tf32(o[0][j], pa[0], b0, b1);
                mma_tf32(o[1][j], pa[1], b0, b1);
            }
        }
        bar_g(bid);   // group-local: done reading tiles + mask before overwrite
    }

    // Output: reference's flat (B,H,T,d)->(B,T,C) reshape
#pragma unroll
    for (int mt = 0; mt < 2; ++mt) {
        float inv0 = 1.f / lrow[mt][0], inv1 = 1.f / lrow[mt][1];
#pragma unroll
        for (int row = 0; row < 2; ++row) {
            int q     = q0 + wid * 32 + mt * 16 + gid + row * 8;
            int t_out = h * 128 + (q >> 4);
            int cbase = (q & 15) << 6;
            float inv = row ? inv1 : inv0;
#pragma unroll
            for (int j = 0; j < 8; ++j) {
                int dd = j * 8 + 2 * tig;
                float2 v = make_float2(o[mt][j][2 * row] * inv,
                                       o[mt][j][2 * row + 1] * inv);
                *(float2*)(out + (size_t)(b * T_ + t_out) * C_ + cbase + dd) = v;
            }
        }
    }
}

// ---------------------------------------------------------------------------
// Launch (stateless)
// ---------------------------------------------------------------------------
extern "C" void kernel_launch(void* const* d_in, const int* in_sizes, int n_in,
                              void* d_out, int out_size)
{
    const float* x    = (const float*)d_in[0];
    const int*   mask = (const int*)d_in[1];
    const float* W    = (const float*)d_in[2];
    const float* bq   = (const float*)d_in[3];
    float*       out  = (float*)d_out;

    cudaFuncSetAttribute(qkv_gemm_mma,
                         cudaFuncAttributeMaxDynamicSharedMemorySize, GEMM_SMEM_BYTES);
    cudaFuncSetAttribute(flash_attn_mma,
                         cudaFuncAttributeMaxDynamicSharedMemorySize, FLASH_SMEM_BYTES);

    // Pre-round X and W to tf32 (no cvts in the GEMM mainloop).
    round_x_pass<<<2048, 256>>>((const float4*)x);
    round_w_pass<<<1024, 256>>>((const float4*)W);

    dim3 g1(N_TOT / 128, M_TOT / 128);   // 24 x 128
    qkv_gemm_mma<<<g1, 256, GEMM_SMEM_BYTES>>>(bq);

    dim3 g2(T_ / 256, B_ * H_);          // 8 x 128
    flash_attn_mma<<<g2, 256, FLASH_SMEM_BYTES>>>(mask, out);
}